// round 1
// baseline (speedup 1.0000x reference)
#include <cuda_runtime.h>

#define TT 1024
#define EE 256
#define DD 64
#define BB 2

// Scratch (device globals: no allocation allowed in kernel_launch)
__device__ float g_qpb[BB * TT * DD];   // qp + b1, row-major [row][d]
__device__ float g_kpT[BB * DD * TT];   // kp transposed   [b][d][t]
__device__ float g_v  [BB * TT * DD];   // v, row-major    [row][dv]

// ---------------------------------------------------------------------------
// Kernel 1: fused projections. 4 rows per block, 64 threads.
//   q = relu(x Wq + bq); k = relu(x Wk + bk); v = x Wv + bv
//   qp = q W1[:D] + b1 ;  kp = k W1[D:]
// ---------------------------------------------------------------------------
__global__ __launch_bounds__(64) void proj_kernel(
    const float* __restrict__ x,
    const float* __restrict__ Wq, const float* __restrict__ bq,
    const float* __restrict__ Wk, const float* __restrict__ bk,
    const float* __restrict__ Wv, const float* __restrict__ bv,
    const float* __restrict__ W1, const float* __restrict__ b1)
{
    __shared__ float x_s[4][EE];
    __shared__ float q_s[4][DD];
    __shared__ float k_s[4][DD];

    const int r0 = blockIdx.x * 4;
    const int t  = threadIdx.x;

    // stage 4 rows of x (contiguous in memory)
    #pragma unroll
    for (int u = 0; u < 16; u++) {
        int idx = t + u * 64;
        x_s[idx >> 8][idx & 255] = x[r0 * EE + idx];
    }
    __syncthreads();

    // Phase A: q, k, v. threads 0..47: which = t/16 in {q,k,v}, 4 d-outputs each.
    if (t < 48) {
        const int which = t >> 4;
        const int d4    = t & 15;
        const float4* W4 = (const float4*)(which == 0 ? Wq : (which == 1 ? Wk : Wv));
        const float4* b4 = (const float4*)(which == 0 ? bq : (which == 1 ? bk : bv));

        float4 acc[4];
        #pragma unroll
        for (int r = 0; r < 4; r++) acc[r] = make_float4(0.f, 0.f, 0.f, 0.f);

        for (int e = 0; e < EE; e++) {
            float4 w = W4[e * 16 + d4];
            #pragma unroll
            for (int r = 0; r < 4; r++) {
                float xv = x_s[r][e];
                acc[r].x = fmaf(xv, w.x, acc[r].x);
                acc[r].y = fmaf(xv, w.y, acc[r].y);
                acc[r].z = fmaf(xv, w.z, acc[r].z);
                acc[r].w = fmaf(xv, w.w, acc[r].w);
            }
        }
        float4 bias = b4[d4];
        #pragma unroll
        for (int r = 0; r < 4; r++) {
            float4 o;
            o.x = acc[r].x + bias.x;
            o.y = acc[r].y + bias.y;
            o.z = acc[r].z + bias.z;
            o.w = acc[r].w + bias.w;
            if (which == 2) {
                *(float4*)&g_v[(r0 + r) * DD + d4 * 4] = o;
            } else {
                o.x = fmaxf(o.x, 0.f);
                o.y = fmaxf(o.y, 0.f);
                o.z = fmaxf(o.z, 0.f);
                o.w = fmaxf(o.w, 0.f);
                if (which == 0) *(float4*)&q_s[r][d4 * 4] = o;
                else            *(float4*)&k_s[r][d4 * 4] = o;
            }
        }
    }
    __syncthreads();

    // Phase B: qp (with b1 folded) and kp. threads 0..31.
    if (t < 32) {
        const int sel = t >> 4;      // 0 = qp, 1 = kp
        const int d4  = t & 15;

        float4 acc[4];
        #pragma unroll
        for (int r = 0; r < 4; r++) acc[r] = make_float4(0.f, 0.f, 0.f, 0.f);

        const float (*src)[DD] = (sel == 0) ? q_s : k_s;
        const float4* W14 = (const float4*)W1 + sel * 64 * 16;

        for (int dd = 0; dd < DD; dd++) {
            float4 w = W14[dd * 16 + d4];
            #pragma unroll
            for (int r = 0; r < 4; r++) {
                float qv = src[r][dd];
                acc[r].x = fmaf(qv, w.x, acc[r].x);
                acc[r].y = fmaf(qv, w.y, acc[r].y);
                acc[r].z = fmaf(qv, w.z, acc[r].z);
                acc[r].w = fmaf(qv, w.w, acc[r].w);
            }
        }

        if (sel == 0) {
            float4 bias = ((const float4*)b1)[d4];
            #pragma unroll
            for (int r = 0; r < 4; r++) {
                float4 o;
                o.x = acc[r].x + bias.x;
                o.y = acc[r].y + bias.y;
                o.z = acc[r].z + bias.z;
                o.w = acc[r].w + bias.w;
                *(float4*)&g_qpb[(r0 + r) * DD + d4 * 4] = o;
            }
        } else {
            const int b  = r0 >> 10;
            const int tb = r0 & 1023;
            #pragma unroll
            for (int r = 0; r < 4; r++) {
                g_kpT[(b * DD + d4 * 4 + 0) * TT + tb + r] = acc[r].x;
                g_kpT[(b * DD + d4 * 4 + 1) * TT + tb + r] = acc[r].y;
                g_kpT[(b * DD + d4 * 4 + 2) * TT + tb + r] = acc[r].z;
                g_kpT[(b * DD + d4 * 4 + 3) * TT + tb + r] = acc[r].w;
            }
        }
    }
}

// ---------------------------------------------------------------------------
// Kernel 2: fused pairwise score + causal online softmax + PV.
// 1 query row per warp, 4 warps/block, 32-key chunks.
// ---------------------------------------------------------------------------
__global__ __launch_bounds__(128, 3) void attn_kernel(
    const float* __restrict__ W2, float* __restrict__ out)
{
    __shared__ float kp_s[DD * 32];   // [d][j]
    __shared__ float v_s [32 * DD];   // [j][dv]
    __shared__ float p_s [4][32];

    // heavy-tiles-first to fix causal imbalance tail
    const int tile = (int)gridDim.x - 1 - (int)blockIdx.x;
    const int b    = tile >> 8;           // 256 tiles per batch
    const int i0   = (tile & 255) * 4;
    const int wid  = threadIdx.x >> 5;
    const int lane = threadIdx.x & 31;
    const int i    = i0 + wid;            // this warp's query row

    // query row + w2 fully in registers (compile-time indexed)
    float qreg[DD], w2reg[DD];
    #pragma unroll
    for (int d4 = 0; d4 < 16; d4++) {
        float4 qv = *(const float4*)&g_qpb[(b * TT + i) * DD + d4 * 4];
        qreg[4 * d4 + 0] = qv.x; qreg[4 * d4 + 1] = qv.y;
        qreg[4 * d4 + 2] = qv.z; qreg[4 * d4 + 3] = qv.w;
        float4 wv = ((const float4*)W2)[d4];
        w2reg[4 * d4 + 0] = wv.x; w2reg[4 * d4 + 1] = wv.y;
        w2reg[4 * d4 + 2] = wv.z; w2reg[4 * d4 + 3] = wv.w;
    }

    const float* kpT_b = g_kpT + b * DD * TT;
    const float* v_b   = g_v   + b * TT * DD;

    const float NEG_INF = __int_as_float(0xff800000);
    float m = NEG_INF, l = 0.f, ox = 0.f, oy = 0.f;

    const int nchunks = (i0 + 3) / 32 + 1;
    for (int c = 0; c < nchunks; c++) {
        const int j0 = c * 32;
        __syncthreads();
        // stage kp chunk (d-major, direct coalesced copy thanks to g_kpT layout)
        #pragma unroll
        for (int u = 0; u < 4; u++) {
            int idx = (int)threadIdx.x + u * 128;      // 0..511 float4s
            int d = idx >> 3, cc = idx & 7;
            ((float4*)kp_s)[idx] = *(const float4*)(kpT_b + d * TT + j0 + cc * 4);
        }
        // stage v chunk (row-major)
        #pragma unroll
        for (int u = 0; u < 4; u++) {
            int idx = (int)threadIdx.x + u * 128;
            ((float4*)v_s)[idx] = *(const float4*)(v_b + j0 * DD + idx * 4);
        }
        __syncthreads();

        if (j0 <= i) {
            // score for key j = j0 + lane
            float a0 = 0.f, a1 = 0.f;
            #pragma unroll
            for (int d = 0; d < DD; d += 2) {
                float s0 = qreg[d]     + kp_s[d * 32 + lane];
                float s1 = qreg[d + 1] + kp_s[(d + 1) * 32 + lane];
                a0 = fmaf(fmaxf(s0, 0.f), w2reg[d],     a0);
                a1 = fmaf(fmaxf(s1, 0.f), w2reg[d + 1], a1);
            }
            const int j = j0 + lane;
            float s = (j <= i) ? (a0 + a1) : NEG_INF;

            // online softmax
            float cm = s;
            #pragma unroll
            for (int off = 16; off; off >>= 1)
                cm = fmaxf(cm, __shfl_xor_sync(0xffffffffu, cm, off));
            float nm   = fmaxf(m, cm);
            float corr = __expf(m - nm);
            float p    = __expf(s - nm);
            float rs = p;
            #pragma unroll
            for (int off = 16; off; off >>= 1)
                rs += __shfl_xor_sync(0xffffffffu, rs, off);
            l  = fmaf(l, corr, rs);
            ox *= corr; oy *= corr;

            p_s[wid][lane] = p;
            __syncwarp();
            // PV: lane owns dv = 2*lane, 2*lane+1
            #pragma unroll
            for (int jj = 0; jj < 32; jj++) {
                float pj  = p_s[wid][jj];
                float2 vv = *(const float2*)&v_s[jj * DD + lane * 2];
                ox = fmaf(pj, vv.x, ox);
                oy = fmaf(pj, vv.y, oy);
            }
            m = nm;
        }
    }

    float inv = 1.0f / l;
    float2 o2; o2.x = ox * inv; o2.y = oy * inv;
    *(float2*)&out[(b * TT + i) * DD + lane * 2] = o2;
}

// ---------------------------------------------------------------------------
extern "C" void kernel_launch(void* const* d_in, const int* in_sizes, int n_in,
                              void* d_out, int out_size)
{
    const float* x  = (const float*)d_in[0];
    const float* Wq = (const float*)d_in[1];
    const float* bq = (const float*)d_in[2];
    const float* Wk = (const float*)d_in[3];
    const float* bk = (const float*)d_in[4];
    const float* Wv = (const float*)d_in[5];
    const float* bv = (const float*)d_in[6];
    const float* W1 = (const float*)d_in[7];
    const float* b1 = (const float*)d_in[8];
    const float* W2 = (const float*)d_in[9];
    // b2 (d_in[10]) is a constant shift on scores: cancels in softmax.

    proj_kernel<<<BB * TT / 4, 64>>>(x, Wq, bq, Wk, bk, Wv, bv, W1, b1);
    attn_kernel<<<BB * TT / 4, 128>>>(W2, (float*)d_out);
}

// round 2
// speedup vs baseline: 1.2437x; 1.2437x over previous
#include <cuda_runtime.h>

#define TT 1024
#define EE 256
#define DD 64
#define BB 2
#define JCH 64   // keys per chunk

// Scratch (device globals: no allocation allowed in kernel_launch)
__device__ float g_qpb[BB * TT * DD];   // qp + b1, row-major [row][d]
__device__ float g_kpT[BB * DD * TT];   // kp transposed   [b][d][t]
__device__ float g_v  [BB * TT * DD];   // v, row-major    [row][dv]

__device__ __forceinline__ void cp16(float* dst, const float* src) {
    unsigned d = (unsigned)__cvta_generic_to_shared(dst);
    asm volatile("cp.async.cg.shared.global [%0], [%1], 16;" :: "r"(d), "l"(src));
}
__device__ __forceinline__ void cp_commit() { asm volatile("cp.async.commit_group;"); }
__device__ __forceinline__ void cp_wait_all() { asm volatile("cp.async.wait_group 0;"); }

// ---------------------------------------------------------------------------
// Kernel 1: fused projections (unchanged from R1 — ~12us, not the bottleneck yet)
// ---------------------------------------------------------------------------
__global__ __launch_bounds__(64) void proj_kernel(
    const float* __restrict__ x,
    const float* __restrict__ Wq, const float* __restrict__ bq,
    const float* __restrict__ Wk, const float* __restrict__ bk,
    const float* __restrict__ Wv, const float* __restrict__ bv,
    const float* __restrict__ W1, const float* __restrict__ b1)
{
    __shared__ float x_s[4][EE];
    __shared__ float q_s[4][DD];
    __shared__ float k_s[4][DD];

    const int r0 = blockIdx.x * 4;
    const int t  = threadIdx.x;

    #pragma unroll
    for (int u = 0; u < 16; u++) {
        int idx = t + u * 64;
        x_s[idx >> 8][idx & 255] = x[r0 * EE + idx];
    }
    __syncthreads();

    if (t < 48) {
        const int which = t >> 4;
        const int d4    = t & 15;
        const float4* W4 = (const float4*)(which == 0 ? Wq : (which == 1 ? Wk : Wv));
        const float4* b4 = (const float4*)(which == 0 ? bq : (which == 1 ? bk : bv));

        float4 acc[4];
        #pragma unroll
        for (int r = 0; r < 4; r++) acc[r] = make_float4(0.f, 0.f, 0.f, 0.f);

        for (int e = 0; e < EE; e++) {
            float4 w = W4[e * 16 + d4];
            #pragma unroll
            for (int r = 0; r < 4; r++) {
                float xv = x_s[r][e];
                acc[r].x = fmaf(xv, w.x, acc[r].x);
                acc[r].y = fmaf(xv, w.y, acc[r].y);
                acc[r].z = fmaf(xv, w.z, acc[r].z);
                acc[r].w = fmaf(xv, w.w, acc[r].w);
            }
        }
        float4 bias = b4[d4];
        #pragma unroll
        for (int r = 0; r < 4; r++) {
            float4 o;
            o.x = acc[r].x + bias.x;
            o.y = acc[r].y + bias.y;
            o.z = acc[r].z + bias.z;
            o.w = acc[r].w + bias.w;
            if (which == 2) {
                *(float4*)&g_v[(r0 + r) * DD + d4 * 4] = o;
            } else {
                o.x = fmaxf(o.x, 0.f);
                o.y = fmaxf(o.y, 0.f);
                o.z = fmaxf(o.z, 0.f);
                o.w = fmaxf(o.w, 0.f);
                if (which == 0) *(float4*)&q_s[r][d4 * 4] = o;
                else            *(float4*)&k_s[r][d4 * 4] = o;
            }
        }
    }
    __syncthreads();

    if (t < 32) {
        const int sel = t >> 4;      // 0 = qp, 1 = kp
        const int d4  = t & 15;

        float4 acc[4];
        #pragma unroll
        for (int r = 0; r < 4; r++) acc[r] = make_float4(0.f, 0.f, 0.f, 0.f);

        const float (*src)[DD] = (sel == 0) ? q_s : k_s;
        const float4* W14 = (const float4*)W1 + sel * 64 * 16;

        for (int dd = 0; dd < DD; dd++) {
            float4 w = W14[dd * 16 + d4];
            #pragma unroll
            for (int r = 0; r < 4; r++) {
                float qv = src[r][dd];
                acc[r].x = fmaf(qv, w.x, acc[r].x);
                acc[r].y = fmaf(qv, w.y, acc[r].y);
                acc[r].z = fmaf(qv, w.z, acc[r].z);
                acc[r].w = fmaf(qv, w.w, acc[r].w);
            }
        }

        if (sel == 0) {
            float4 bias = ((const float4*)b1)[d4];
            #pragma unroll
            for (int r = 0; r < 4; r++) {
                float4 o;
                o.x = acc[r].x + bias.x;
                o.y = acc[r].y + bias.y;
                o.z = acc[r].z + bias.z;
                o.w = acc[r].w + bias.w;
                *(float4*)&g_qpb[(r0 + r) * DD + d4 * 4] = o;
            }
        } else {
            const int b  = r0 >> 10;
            const int tb = r0 & 1023;
            #pragma unroll
            for (int r = 0; r < 4; r++) {
                g_kpT[(b * DD + d4 * 4 + 0) * TT + tb + r] = acc[r].x;
                g_kpT[(b * DD + d4 * 4 + 1) * TT + tb + r] = acc[r].y;
                g_kpT[(b * DD + d4 * 4 + 2) * TT + tb + r] = acc[r].z;
                g_kpT[(b * DD + d4 * 4 + 3) * TT + tb + r] = acc[r].w;
            }
        }
    }
}

// ---------------------------------------------------------------------------
// Kernel 2: score + causal online softmax + PV.
// 1 query/warp, 4 warps/block, J=64 key chunks, double-buffered cp.async kp
// staging, w2 in smem (regs ~100 -> 4 blocks/SM), v via __ldg.
// ---------------------------------------------------------------------------
__global__ __launch_bounds__(128, 4) void attn_kernel(
    const float* __restrict__ W2, float* __restrict__ out)
{
    __shared__ float kp_s[2][DD][JCH];   // 2 x 16KB double buffer, [d][key]
    __shared__ float w2_s[DD];
    __shared__ float p_s[4][JCH];

    // heavy-tiles-first to fix causal imbalance tail
    const int tile = (int)gridDim.x - 1 - (int)blockIdx.x;
    const int b    = tile >> 8;           // 256 tiles per batch
    const int i0   = (tile & 255) * 4;
    const int t    = threadIdx.x;
    const int wid  = t >> 5;
    const int lane = t & 31;
    const int i    = i0 + wid;            // this warp's query row

    if (t < DD) w2_s[t] = W2[t];

    const float*  kpT_b = g_kpT + b * DD * TT;
    const float2* v2    = (const float2*)(g_v + b * TT * DD);

    // prefetch chunk 0
    #pragma unroll
    for (int u = 0; u < 8; u++) {
        int idx = t + u * 128;            // 0..1023 float4 slots
        int d = idx >> 4, cc = idx & 15;
        cp16(&kp_s[0][d][cc * 4], kpT_b + d * TT + cc * 4);
    }
    cp_commit();

    // query row in registers (compile-time indexed)
    float qreg[DD];
    #pragma unroll
    for (int d4 = 0; d4 < 16; d4++) {
        float4 qv = *(const float4*)&g_qpb[(b * TT + i) * DD + d4 * 4];
        qreg[4 * d4 + 0] = qv.x; qreg[4 * d4 + 1] = qv.y;
        qreg[4 * d4 + 2] = qv.z; qreg[4 * d4 + 3] = qv.w;
    }

    const float NEG_INF = __int_as_float(0xff800000);
    float m = NEG_INF, l = 0.f, ox = 0.f, oy = 0.f;

    const int nch = i0 / JCH + 1;         // block-uniform (covers keys <= i0+3)

    for (int c = 0; c < nch; c++) {
        cp_wait_all();
        __syncthreads();                  // staged chunk c visible to all

        // prefetch chunk c+1 into the other buffer (safe: all warps are past
        // the barrier, hence past their compute on that buffer from c-1)
        if (c + 1 < nch) {
            const int j0n = (c + 1) * JCH;
            #pragma unroll
            for (int u = 0; u < 8; u++) {
                int idx = t + u * 128;
                int d = idx >> 4, cc = idx & 15;
                cp16(&kp_s[(c + 1) & 1][d][cc * 4], kpT_b + d * TT + j0n + cc * 4);
            }
            cp_commit();
        }

        const int j0 = c * JCH;
        const float (*kp)[JCH] = kp_s[c & 1];

        // ---- score for keys j0+2*lane, j0+2*lane+1 (4 independent chains) ----
        float a0 = 0.f, a1 = 0.f, a2 = 0.f, a3 = 0.f;
        #pragma unroll
        for (int d4 = 0; d4 < 16; d4++) {
            float4 w4 = *(const float4*)&w2_s[d4 * 4];
            float2 k0 = *(const float2*)&kp[4 * d4 + 0][2 * lane];
            float2 k1 = *(const float2*)&kp[4 * d4 + 1][2 * lane];
            float2 k2 = *(const float2*)&kp[4 * d4 + 2][2 * lane];
            float2 k3 = *(const float2*)&kp[4 * d4 + 3][2 * lane];
            a0 = fmaf(fmaxf(qreg[4 * d4 + 0] + k0.x, 0.f), w4.x, a0);
            a1 = fmaf(fmaxf(qreg[4 * d4 + 0] + k0.y, 0.f), w4.x, a1);
            a2 = fmaf(fmaxf(qreg[4 * d4 + 1] + k1.x, 0.f), w4.y, a2);
            a3 = fmaf(fmaxf(qreg[4 * d4 + 1] + k1.y, 0.f), w4.y, a3);
            a0 = fmaf(fmaxf(qreg[4 * d4 + 2] + k2.x, 0.f), w4.z, a0);
            a1 = fmaf(fmaxf(qreg[4 * d4 + 2] + k2.y, 0.f), w4.z, a1);
            a2 = fmaf(fmaxf(qreg[4 * d4 + 3] + k3.x, 0.f), w4.w, a2);
            a3 = fmaf(fmaxf(qreg[4 * d4 + 3] + k3.y, 0.f), w4.w, a3);
        }
        float s0 = a0 + a2, s1 = a1 + a3;
        const int j = j0 + 2 * lane;
        s0 = (j     <= i) ? s0 : NEG_INF;
        s1 = (j + 1 <= i) ? s1 : NEG_INF;

        // ---- online softmax over 64 keys (one shfl round per 64 keys) ----
        float cm = fmaxf(s0, s1);
        #pragma unroll
        for (int off = 16; off; off >>= 1)
            cm = fmaxf(cm, __shfl_xor_sync(0xffffffffu, cm, off));
        float nm   = fmaxf(m, cm);
        float corr = __expf(m - nm);
        float p0   = __expf(s0 - nm);
        float p1   = __expf(s1 - nm);
        float rs   = p0 + p1;
        #pragma unroll
        for (int off = 16; off; off >>= 1)
            rs += __shfl_xor_sync(0xffffffffu, rs, off);
        l  = fmaf(l, corr, rs);
        ox *= corr; oy *= corr;

        *(float2*)&p_s[wid][2 * lane] = make_float2(p0, p1);
        __syncwarp();

        // ---- PV: lane owns dv = 2*lane, 2*lane+1; v straight from L1/L2 ----
        const float2* vrow = v2 + j0 * 32 + lane;
        #pragma unroll 8
        for (int jj = 0; jj < JCH; jj++) {
            float  pj = p_s[wid][jj];
            float2 vv = __ldg(&vrow[jj * 32]);
            ox = fmaf(pj, vv.x, ox);
            oy = fmaf(pj, vv.y, oy);
        }
        m = nm;
    }

    float inv = 1.0f / l;
    *(float2*)&out[(b * TT + i) * DD + 2 * lane] = make_float2(ox * inv, oy * inv);
}

// ---------------------------------------------------------------------------
extern "C" void kernel_launch(void* const* d_in, const int* in_sizes, int n_in,
                              void* d_out, int out_size)
{
    const float* x  = (const float*)d_in[0];
    const float* Wq = (const float*)d_in[1];
    const float* bq = (const float*)d_in[2];
    const float* Wk = (const float*)d_in[3];
    const float* bk = (const float*)d_in[4];
    const float* Wv = (const float*)d_in[5];
    const float* bv = (const float*)d_in[6];
    const float* W1 = (const float*)d_in[7];
    const float* b1 = (const float*)d_in[8];
    const float* W2 = (const float*)d_in[9];
    // b2 (d_in[10]) is a constant shift on scores: cancels in softmax.

    proj_kernel<<<BB * TT / 4, 64>>>(x, Wq, bq, Wk, bk, Wv, bv, W1, b1);
    attn_kernel<<<BB * TT / 4, 128>>>(W2, (float*)d_out);
}

// round 5
// speedup vs baseline: 1.5728x; 1.2646x over previous
#include <cuda_runtime.h>

#define TT 1024
#define EE 256
#define DD 64
#define BB 2
#define JCH 64   // keys per chunk

// Scratch (device globals: no allocation allowed in kernel_launch)
__device__ float g_qpb[BB * TT * DD];   // qp + b1, row-major [row][d]
__device__ float g_kpT[BB * DD * TT];   // kp transposed   [b][d][t]
__device__ float g_v  [BB * TT * DD];   // v, row-major    [row][dv]

__device__ __forceinline__ void cp16(float* dst, const float* src) {
    unsigned d = (unsigned)__cvta_generic_to_shared(dst);
    asm volatile("cp.async.cg.shared.global [%0], [%1], 16;" :: "r"(d), "l"(src));
}
__device__ __forceinline__ void cp_commit() { asm volatile("cp.async.commit_group;"); }
__device__ __forceinline__ void cp_wait_all() { asm volatile("cp.async.wait_group 0;"); }

// Warp-wide float max via integer redux.sync (f32 redux doesn't exist).
// Order-preserving monotonic map: x>=0 -> bits|0x80000000, x<0 -> ~bits.
__device__ __forceinline__ float warp_max_f32(float x) {
    unsigned ix = __float_as_uint(x);
    ix = (ix & 0x80000000u) ? ~ix : (ix | 0x80000000u);
    unsigned r = __reduce_max_sync(0xffffffffu, ix);
    r = (r & 0x80000000u) ? (r & 0x7fffffffu) : ~r;
    return __uint_as_float(r);
}

// ---------------------------------------------------------------------------
// Kernel 1: fused projections (unchanged — optimize after attn stops dominating)
// ---------------------------------------------------------------------------
__global__ __launch_bounds__(64) void proj_kernel(
    const float* __restrict__ x,
    const float* __restrict__ Wq, const float* __restrict__ bq,
    const float* __restrict__ Wk, const float* __restrict__ bk,
    const float* __restrict__ Wv, const float* __restrict__ bv,
    const float* __restrict__ W1, const float* __restrict__ b1)
{
    __shared__ float x_s[4][EE];
    __shared__ float q_s[4][DD];
    __shared__ float k_s[4][DD];

    const int r0 = blockIdx.x * 4;
    const int t  = threadIdx.x;

    #pragma unroll
    for (int u = 0; u < 16; u++) {
        int idx = t + u * 64;
        x_s[idx >> 8][idx & 255] = x[r0 * EE + idx];
    }
    __syncthreads();

    if (t < 48) {
        const int which = t >> 4;
        const int d4    = t & 15;
        const float4* W4 = (const float4*)(which == 0 ? Wq : (which == 1 ? Wk : Wv));
        const float4* b4 = (const float4*)(which == 0 ? bq : (which == 1 ? bk : bv));

        float4 acc[4];
        #pragma unroll
        for (int r = 0; r < 4; r++) acc[r] = make_float4(0.f, 0.f, 0.f, 0.f);

        for (int e = 0; e < EE; e++) {
            float4 w = W4[e * 16 + d4];
            #pragma unroll
            for (int r = 0; r < 4; r++) {
                float xv = x_s[r][e];
                acc[r].x = fmaf(xv, w.x, acc[r].x);
                acc[r].y = fmaf(xv, w.y, acc[r].y);
                acc[r].z = fmaf(xv, w.z, acc[r].z);
                acc[r].w = fmaf(xv, w.w, acc[r].w);
            }
        }
        float4 bias = b4[d4];
        #pragma unroll
        for (int r = 0; r < 4; r++) {
            float4 o;
            o.x = acc[r].x + bias.x;
            o.y = acc[r].y + bias.y;
            o.z = acc[r].z + bias.z;
            o.w = acc[r].w + bias.w;
            if (which == 2) {
                *(float4*)&g_v[(r0 + r) * DD + d4 * 4] = o;
            } else {
                o.x = fmaxf(o.x, 0.f);
                o.y = fmaxf(o.y, 0.f);
                o.z = fmaxf(o.z, 0.f);
                o.w = fmaxf(o.w, 0.f);
                if (which == 0) *(float4*)&q_s[r][d4 * 4] = o;
                else            *(float4*)&k_s[r][d4 * 4] = o;
            }
        }
    }
    __syncthreads();

    if (t < 32) {
        const int sel = t >> 4;      // 0 = qp, 1 = kp
        const int d4  = t & 15;

        float4 acc[4];
        #pragma unroll
        for (int r = 0; r < 4; r++) acc[r] = make_float4(0.f, 0.f, 0.f, 0.f);

        const float (*src)[DD] = (sel == 0) ? q_s : k_s;
        const float4* W14 = (const float4*)W1 + sel * 64 * 16;

        for (int dd = 0; dd < DD; dd++) {
            float4 w = W14[dd * 16 + d4];
            #pragma unroll
            for (int r = 0; r < 4; r++) {
                float qv = src[r][dd];
                acc[r].x = fmaf(qv, w.x, acc[r].x);
                acc[r].y = fmaf(qv, w.y, acc[r].y);
                acc[r].z = fmaf(qv, w.z, acc[r].z);
                acc[r].w = fmaf(qv, w.w, acc[r].w);
            }
        }

        if (sel == 0) {
            float4 bias = ((const float4*)b1)[d4];
            #pragma unroll
            for (int r = 0; r < 4; r++) {
                float4 o;
                o.x = acc[r].x + bias.x;
                o.y = acc[r].y + bias.y;
                o.z = acc[r].z + bias.z;
                o.w = acc[r].w + bias.w;
                *(float4*)&g_qpb[(r0 + r) * DD + d4 * 4] = o;
            }
        } else {
            const int b  = r0 >> 10;
            const int tb = r0 & 1023;
            #pragma unroll
            for (int r = 0; r < 4; r++) {
                g_kpT[(b * DD + d4 * 4 + 0) * TT + tb + r] = acc[r].x;
                g_kpT[(b * DD + d4 * 4 + 1) * TT + tb + r] = acc[r].y;
                g_kpT[(b * DD + d4 * 4 + 2) * TT + tb + r] = acc[r].z;
                g_kpT[(b * DD + d4 * 4 + 3) * TT + tb + r] = acc[r].w;
            }
        }
    }
}

// ---------------------------------------------------------------------------
// Kernel 2: score + causal online softmax + PV.
// 1 query/warp, 4 warps/block, J=64 chunks, double-buffered cp.async kp AND v,
// lane-local softmax sum (no per-chunk sum tree), single-redux max.
// Dynamic smem: 2*16KB kp + 2*16KB v + p + w2 = ~66KB.
// ---------------------------------------------------------------------------
#define SMEM_FLOATS (2 * DD * JCH + 2 * JCH * DD + 4 * JCH + DD + 4)
#define SMEM_BYTES  (SMEM_FLOATS * 4)

__global__ __launch_bounds__(128, 3) void attn_kernel(
    const float* __restrict__ W2, float* __restrict__ out)
{
    extern __shared__ __align__(16) float smem[];
    float (*kp_s)[DD][JCH] = (float (*)[DD][JCH])smem;                  // [2][d][j]
    float (*v_s)[JCH][DD]  = (float (*)[JCH][DD])(smem + 2 * DD * JCH); // [2][j][dv]
    float (*p_s)[JCH]      = (float (*)[JCH])(smem + 4 * DD * JCH);     // [4][j]
    float *w2_s            = smem + 4 * DD * JCH + 4 * JCH;

    const int tile = (int)gridDim.x - 1 - (int)blockIdx.x;   // heavy-first
    const int b    = tile >> 8;
    const int i0   = (tile & 255) * 4;
    const int t    = threadIdx.x;
    const int wid  = t >> 5;
    const int lane = t & 31;
    const int i    = i0 + wid;

    if (t < DD) w2_s[t] = W2[t];

    const float* kpT_b = g_kpT + b * DD * TT;
    const float* v_b   = g_v   + b * TT * DD;

    // prefetch chunk 0 (kp + v)
    #pragma unroll
    for (int u = 0; u < 8; u++) {
        int idx = t + u * 128;               // 0..1023 float4 slots
        int d = idx >> 4, cc = idx & 15;
        cp16(&kp_s[0][d][cc * 4], kpT_b + d * TT + cc * 4);
        cp16(&v_s[0][0][0] + idx * 4, v_b + idx * 4);
    }
    cp_commit();

    // query row in registers (compile-time indexed)
    float qreg[DD];
    #pragma unroll
    for (int d4 = 0; d4 < 16; d4++) {
        float4 qv = *(const float4*)&g_qpb[(b * TT + i) * DD + d4 * 4];
        qreg[4 * d4 + 0] = qv.x; qreg[4 * d4 + 1] = qv.y;
        qreg[4 * d4 + 2] = qv.z; qreg[4 * d4 + 3] = qv.w;
    }

    const float NEG_INF = __int_as_float(0xff800000);
    float m = NEG_INF, l = 0.f;
    float oxe = 0.f, oye = 0.f, oxo = 0.f, oyo = 0.f;

    const int nch = i0 / JCH + 1;            // block-uniform

    for (int c = 0; c < nch; c++) {
        cp_wait_all();
        __syncthreads();                      // chunk c staged & visible

        if (c + 1 < nch) {                    // prefetch c+1 into other buffer
            const int j0n = (c + 1) * JCH;
            const int buf = (c + 1) & 1;
            #pragma unroll
            for (int u = 0; u < 8; u++) {
                int idx = t + u * 128;
                int d = idx >> 4, cc = idx & 15;
                cp16(&kp_s[buf][d][cc * 4], kpT_b + d * TT + j0n + cc * 4);
                cp16(&v_s[buf][0][0] + idx * 4, v_b + j0n * DD + idx * 4);
            }
            cp_commit();
        }

        const int j0 = c * JCH;
        const float (*kp)[JCH] = kp_s[c & 1];
        const float (*vv_s)[DD] = v_s[c & 1];

        // ---- scores for keys j0+2*lane, j0+2*lane+1 (4 chains) ----
        float a0 = 0.f, a1 = 0.f, a2 = 0.f, a3 = 0.f;
        #pragma unroll
        for (int d4 = 0; d4 < 16; d4++) {
            float4 w4 = *(const float4*)&w2_s[d4 * 4];
            float2 k0 = *(const float2*)&kp[4 * d4 + 0][2 * lane];
            float2 k1 = *(const float2*)&kp[4 * d4 + 1][2 * lane];
            float2 k2 = *(const float2*)&kp[4 * d4 + 2][2 * lane];
            float2 k3 = *(const float2*)&kp[4 * d4 + 3][2 * lane];
            a0 = fmaf(fmaxf(qreg[4 * d4 + 0] + k0.x, 0.f), w4.x, a0);
            a1 = fmaf(fmaxf(qreg[4 * d4 + 0] + k0.y, 0.f), w4.x, a1);
            a2 = fmaf(fmaxf(qreg[4 * d4 + 1] + k1.x, 0.f), w4.y, a2);
            a3 = fmaf(fmaxf(qreg[4 * d4 + 1] + k1.y, 0.f), w4.y, a3);
            a0 = fmaf(fmaxf(qreg[4 * d4 + 2] + k2.x, 0.f), w4.z, a0);
            a1 = fmaf(fmaxf(qreg[4 * d4 + 2] + k2.y, 0.f), w4.z, a1);
            a2 = fmaf(fmaxf(qreg[4 * d4 + 3] + k3.x, 0.f), w4.w, a2);
            a3 = fmaf(fmaxf(qreg[4 * d4 + 3] + k3.y, 0.f), w4.w, a3);
        }
        float s0 = a0 + a2, s1 = a1 + a3;
        const int j = j0 + 2 * lane;
        s0 = (j     <= i) ? s0 : NEG_INF;
        s1 = (j + 1 <= i) ? s1 : NEG_INF;

        // ---- online softmax: single integer-redux max; lane-local sum ----
        float nm   = fmaxf(m, warp_max_f32(fmaxf(s0, s1)));
        float corr = __expf(m - nm);
        float p0   = __expf(s0 - nm);
        float p1   = __expf(s1 - nm);
        l = fmaf(l, corr, p0 + p1);            // lane-local: summed at the end
        oxe *= corr; oye *= corr; oxo *= corr; oyo *= corr;
        m = nm;

        *(float2*)&p_s[wid][2 * lane] = make_float2(p0, p1);
        __syncwarp();

        // ---- PV: lane owns dv = 2*lane, 2*lane+1; all shared memory ----
        #pragma unroll
        for (int jj = 0; jj < JCH; jj += 2) {
            float  pe = p_s[wid][jj];
            float  po = p_s[wid][jj + 1];
            float2 ve = *(const float2*)&vv_s[jj][2 * lane];
            float2 vo = *(const float2*)&vv_s[jj + 1][2 * lane];
            oxe = fmaf(pe, ve.x, oxe);
            oye = fmaf(pe, ve.y, oye);
            oxo = fmaf(po, vo.x, oxo);
            oyo = fmaf(po, vo.y, oyo);
        }
    }

    // final cross-lane sum of l (once per kernel)
    float lt = l;
    #pragma unroll
    for (int off = 16; off; off >>= 1)
        lt += __shfl_xor_sync(0xffffffffu, lt, off);

    float inv = 1.0f / lt;
    *(float2*)&out[(b * TT + i) * DD + 2 * lane] =
        make_float2((oxe + oxo) * inv, (oye + oyo) * inv);
}

// ---------------------------------------------------------------------------
extern "C" void kernel_launch(void* const* d_in, const int* in_sizes, int n_in,
                              void* d_out, int out_size)
{
    const float* x  = (const float*)d_in[0];
    const float* Wq = (const float*)d_in[1];
    const float* bq = (const float*)d_in[2];
    const float* Wk = (const float*)d_in[3];
    const float* bk = (const float*)d_in[4];
    const float* Wv = (const float*)d_in[5];
    const float* bv = (const float*)d_in[6];
    const float* W1 = (const float*)d_in[7];
    const float* b1 = (const float*)d_in[8];
    const float* W2 = (const float*)d_in[9];
    // b2 (d_in[10]) is a constant shift on scores: cancels in softmax.

    (void)cudaFuncSetAttribute(attn_kernel,
                               cudaFuncAttributeMaxDynamicSharedMemorySize,
                               SMEM_BYTES);

    proj_kernel<<<BB * TT / 4, 64>>>(x, Wq, bq, Wk, bk, Wv, bv, W1, b1);
    attn_kernel<<<BB * TT / 4, 128, SMEM_BYTES>>>(W2, (float*)d_out);
}

// round 6
// speedup vs baseline: 1.8917x; 1.2028x over previous
#include <cuda_runtime.h>

#define TT 1024
#define EE 256
#define DD 64
#define BB 2
#define JCH 64   // keys per chunk

// Scratch (device globals: no allocation allowed in kernel_launch)
__device__ float g_qpb[BB * TT * DD];   // qp + b1, row-major [row][d]
__device__ float g_kpT[BB * DD * TT];   // kp transposed   [b][d][t]
__device__ float g_v  [BB * TT * DD];   // v, row-major    [row][dv]

__device__ __forceinline__ void cp16(float* dst, const float* src) {
    unsigned d = (unsigned)__cvta_generic_to_shared(dst);
    asm volatile("cp.async.cg.shared.global [%0], [%1], 16;" :: "r"(d), "l"(src));
}
__device__ __forceinline__ void cp_commit() { asm volatile("cp.async.commit_group;"); }
__device__ __forceinline__ void cp_wait_all() { asm volatile("cp.async.wait_group 0;"); }

// Warp-wide float max via integer redux.sync (f32 redux doesn't exist).
__device__ __forceinline__ float warp_max_f32(float x) {
    unsigned ix = __float_as_uint(x);
    ix = (ix & 0x80000000u) ? ~ix : (ix | 0x80000000u);
    unsigned r = __reduce_max_sync(0xffffffffu, ix);
    r = (r & 0x80000000u) ? (r & 0x7fffffffu) : ~r;
    return __uint_as_float(r);
}

// ---------------------------------------------------------------------------
// Kernel 1: fused projections. 2 rows/block x 1024 blocks (more warps/SM).
// ---------------------------------------------------------------------------
__global__ __launch_bounds__(64) void proj_kernel(
    const float* __restrict__ x,
    const float* __restrict__ Wq, const float* __restrict__ bq,
    const float* __restrict__ Wk, const float* __restrict__ bk,
    const float* __restrict__ Wv, const float* __restrict__ bv,
    const float* __restrict__ W1, const float* __restrict__ b1)
{
    __shared__ float x_s[2][EE];
    __shared__ float q_s[2][DD];
    __shared__ float k_s[2][DD];

    const int r0 = blockIdx.x * 2;
    const int t  = threadIdx.x;

    #pragma unroll
    for (int u = 0; u < 2; u++) {
        int idx = t + u * 64;                 // 0..127 float4s of 2 rows
        ((float4*)x_s)[idx] = ((const float4*)(x + r0 * EE))[idx];
    }
    __syncthreads();

    if (t < 48) {
        const int which = t >> 4;
        const int d4    = t & 15;
        const float4* W4 = (const float4*)(which == 0 ? Wq : (which == 1 ? Wk : Wv));
        const float4* b4 = (const float4*)(which == 0 ? bq : (which == 1 ? bk : bv));

        float4 acc[2];
        #pragma unroll
        for (int r = 0; r < 2; r++) acc[r] = make_float4(0.f, 0.f, 0.f, 0.f);

        for (int e = 0; e < EE; e++) {
            float4 w = W4[e * 16 + d4];
            #pragma unroll
            for (int r = 0; r < 2; r++) {
                float xv = x_s[r][e];
                acc[r].x = fmaf(xv, w.x, acc[r].x);
                acc[r].y = fmaf(xv, w.y, acc[r].y);
                acc[r].z = fmaf(xv, w.z, acc[r].z);
                acc[r].w = fmaf(xv, w.w, acc[r].w);
            }
        }
        float4 bias = b4[d4];
        #pragma unroll
        for (int r = 0; r < 2; r++) {
            float4 o;
            o.x = acc[r].x + bias.x;
            o.y = acc[r].y + bias.y;
            o.z = acc[r].z + bias.z;
            o.w = acc[r].w + bias.w;
            if (which == 2) {
                *(float4*)&g_v[(r0 + r) * DD + d4 * 4] = o;
            } else {
                o.x = fmaxf(o.x, 0.f);
                o.y = fmaxf(o.y, 0.f);
                o.z = fmaxf(o.z, 0.f);
                o.w = fmaxf(o.w, 0.f);
                if (which == 0) *(float4*)&q_s[r][d4 * 4] = o;
                else            *(float4*)&k_s[r][d4 * 4] = o;
            }
        }
    }
    __syncthreads();

    if (t < 32) {
        const int sel = t >> 4;      // 0 = qp, 1 = kp
        const int d4  = t & 15;

        float4 acc[2];
        #pragma unroll
        for (int r = 0; r < 2; r++) acc[r] = make_float4(0.f, 0.f, 0.f, 0.f);

        const float (*src)[DD] = (sel == 0) ? q_s : k_s;
        const float4* W14 = (const float4*)W1 + sel * 64 * 16;

        for (int dd = 0; dd < DD; dd++) {
            float4 w = W14[dd * 16 + d4];
            #pragma unroll
            for (int r = 0; r < 2; r++) {
                float qv = src[r][dd];
                acc[r].x = fmaf(qv, w.x, acc[r].x);
                acc[r].y = fmaf(qv, w.y, acc[r].y);
                acc[r].z = fmaf(qv, w.z, acc[r].z);
                acc[r].w = fmaf(qv, w.w, acc[r].w);
            }
        }

        if (sel == 0) {
            float4 bias = ((const float4*)b1)[d4];
            #pragma unroll
            for (int r = 0; r < 2; r++) {
                float4 o;
                o.x = acc[r].x + bias.x;
                o.y = acc[r].y + bias.y;
                o.z = acc[r].z + bias.z;
                o.w = acc[r].w + bias.w;
                *(float4*)&g_qpb[(r0 + r) * DD + d4 * 4] = o;
            }
        } else {
            const int b  = r0 >> 10;
            const int tb = r0 & 1023;
            #pragma unroll
            for (int r = 0; r < 2; r++) {
                g_kpT[(b * DD + d4 * 4 + 0) * TT + tb + r] = acc[r].x;
                g_kpT[(b * DD + d4 * 4 + 1) * TT + tb + r] = acc[r].y;
                g_kpT[(b * DD + d4 * 4 + 2) * TT + tb + r] = acc[r].z;
                g_kpT[(b * DD + d4 * 4 + 3) * TT + tb + r] = acc[r].w;
            }
        }
    }
}

// ---------------------------------------------------------------------------
// Kernel 2: 2 queries per warp — every kp/v shared-memory read feeds two
// queries (halves SMEM bytes/pair, the R5 bottleneck). Block = 64 threads
// (2 warps, 4 query rows), grid 512. q rows + w2 read as smem broadcasts.
// ---------------------------------------------------------------------------
#define SMEM_FLOATS (2 * DD * JCH + 2 * JCH * DD + 4 * JCH + 4 * DD + DD + 4)
#define SMEM_BYTES  (SMEM_FLOATS * 4)

__global__ __launch_bounds__(64, 3) void attn_kernel(
    const float* __restrict__ W2, float* __restrict__ out)
{
    extern __shared__ __align__(16) float smem[];
    float (*kp_s)[DD][JCH] = (float (*)[DD][JCH])smem;                  // [2][d][j]
    float (*v_s)[JCH][DD]  = (float (*)[JCH][DD])(smem + 2 * DD * JCH); // [2][j][dv]
    float (*p_s)[JCH]      = (float (*)[JCH])(smem + 4 * DD * JCH);     // [4][j]
    float (*q_s)[DD]       = (float (*)[DD])(smem + 4 * DD * JCH + 4 * JCH); // [4][d]
    float *w2_s            = smem + 4 * DD * JCH + 4 * JCH + 4 * DD;

    const int tile = (int)gridDim.x - 1 - (int)blockIdx.x;   // heavy-first
    const int b    = tile >> 8;
    const int i0   = (tile & 255) * 4;
    const int t    = threadIdx.x;
    const int wid  = t >> 5;
    const int lane = t & 31;
    const int ia   = i0 + wid * 2;       // this warp's two query rows
    const int ib   = ia + 1;

    if (t < DD) w2_s[t] = W2[t];
    // stage 4 query rows (64 float4s, one per thread)
    ((float4*)q_s)[t] = ((const float4*)(g_qpb + (b * TT + i0) * DD))[t];

    const float* kpT_b = g_kpT + b * DD * TT;
    const float* v_b   = g_v   + b * TT * DD;

    // prefetch chunk 0 (kp + v)
    #pragma unroll
    for (int u = 0; u < 16; u++) {
        int idx = t + u * 64;                // 0..1023 float4 slots
        int d = idx >> 4, cc = idx & 15;
        cp16(&kp_s[0][d][cc * 4], kpT_b + d * TT + cc * 4);
        cp16(&v_s[0][0][0] + idx * 4, v_b + idx * 4);
    }
    cp_commit();

    const float NEG_INF = __int_as_float(0xff800000);
    float ma = NEG_INF, la = 0.f, mb = NEG_INF, lb = 0.f;
    float axe = 0.f, aye = 0.f, axo = 0.f, ayo = 0.f;
    float bxe = 0.f, bye = 0.f, bxo = 0.f, byo = 0.f;

    const int nch = i0 / JCH + 1;            // block-uniform

    const float4* qa4 = (const float4*)q_s[wid * 2];
    const float4* qb4 = (const float4*)q_s[wid * 2 + 1];
    const float4* w24 = (const float4*)w2_s;

    for (int c = 0; c < nch; c++) {
        cp_wait_all();
        __syncthreads();                      // chunk c staged & visible

        if (c + 1 < nch) {                    // prefetch c+1 into other buffer
            const int j0n = (c + 1) * JCH;
            const int buf = (c + 1) & 1;
            #pragma unroll
            for (int u = 0; u < 16; u++) {
                int idx = t + u * 64;
                int d = idx >> 4, cc = idx & 15;
                cp16(&kp_s[buf][d][cc * 4], kpT_b + d * TT + j0n + cc * 4);
                cp16(&v_s[buf][0][0] + idx * 4, v_b + j0n * DD + idx * 4);
            }
            cp_commit();
        }

        const int j0 = c * JCH;
        const float (*kp)[JCH] = kp_s[c & 1];
        const float (*vv_s)[DD] = v_s[c & 1];

        // ---- scores for keys j0+2*lane(+1), queries ia & ib ----
        float a0 = 0.f, a1 = 0.f, a2 = 0.f, a3 = 0.f;
        float b0 = 0.f, b1 = 0.f, b2 = 0.f, b3 = 0.f;
        #pragma unroll
        for (int d4 = 0; d4 < 16; d4++) {
            float4 w4 = w24[d4];
            float4 qa = qa4[d4];
            float4 qb = qb4[d4];
            float2 k0 = *(const float2*)&kp[4 * d4 + 0][2 * lane];
            float2 k1 = *(const float2*)&kp[4 * d4 + 1][2 * lane];
            float2 k2 = *(const float2*)&kp[4 * d4 + 2][2 * lane];
            float2 k3 = *(const float2*)&kp[4 * d4 + 3][2 * lane];
            a0 = fmaf(fmaxf(qa.x + k0.x, 0.f), w4.x, a0);
            a1 = fmaf(fmaxf(qa.x + k0.y, 0.f), w4.x, a1);
            a2 = fmaf(fmaxf(qa.y + k1.x, 0.f), w4.y, a2);
            a3 = fmaf(fmaxf(qa.y + k1.y, 0.f), w4.y, a3);
            a0 = fmaf(fmaxf(qa.z + k2.x, 0.f), w4.z, a0);
            a1 = fmaf(fmaxf(qa.z + k2.y, 0.f), w4.z, a1);
            a2 = fmaf(fmaxf(qa.w + k3.x, 0.f), w4.w, a2);
            a3 = fmaf(fmaxf(qa.w + k3.y, 0.f), w4.w, a3);
            b0 = fmaf(fmaxf(qb.x + k0.x, 0.f), w4.x, b0);
            b1 = fmaf(fmaxf(qb.x + k0.y, 0.f), w4.x, b1);
            b2 = fmaf(fmaxf(qb.y + k1.x, 0.f), w4.y, b2);
            b3 = fmaf(fmaxf(qb.y + k1.y, 0.f), w4.y, b3);
            b0 = fmaf(fmaxf(qb.z + k2.x, 0.f), w4.z, b0);
            b1 = fmaf(fmaxf(qb.z + k2.y, 0.f), w4.z, b1);
            b2 = fmaf(fmaxf(qb.w + k3.x, 0.f), w4.w, b2);
            b3 = fmaf(fmaxf(qb.w + k3.y, 0.f), w4.w, b3);
        }
        const int j = j0 + 2 * lane;
        float s0a = (j     <= ia) ? (a0 + a2) : NEG_INF;
        float s1a = (j + 1 <= ia) ? (a1 + a3) : NEG_INF;
        float s0b = (j     <= ib) ? (b0 + b2) : NEG_INF;
        float s1b = (j + 1 <= ib) ? (b1 + b3) : NEG_INF;

        // ---- online softmax (lane-local sums, one redux max per query) ----
        float nma  = fmaxf(ma, warp_max_f32(fmaxf(s0a, s1a)));
        float nmb  = fmaxf(mb, warp_max_f32(fmaxf(s0b, s1b)));
        float ca   = __expf(ma - nma);
        float cb   = __expf(mb - nmb);
        float p0a  = __expf(s0a - nma), p1a = __expf(s1a - nma);
        float p0b  = __expf(s0b - nmb), p1b = __expf(s1b - nmb);
        la = fmaf(la, ca, p0a + p1a);
        lb = fmaf(lb, cb, p0b + p1b);
        axe *= ca; aye *= ca; axo *= ca; ayo *= ca;
        bxe *= cb; bye *= cb; bxo *= cb; byo *= cb;
        ma = nma; mb = nmb;

        *(float2*)&p_s[wid * 2    ][2 * lane] = make_float2(p0a, p1a);
        *(float2*)&p_s[wid * 2 + 1][2 * lane] = make_float2(p0b, p1b);
        __syncwarp();

        // ---- PV: each v LDS.64 feeds both queries ----
        #pragma unroll
        for (int jj = 0; jj < JCH; jj += 2) {
            float  pae = p_s[wid * 2][jj];
            float  pao = p_s[wid * 2][jj + 1];
            float  pbe = p_s[wid * 2 + 1][jj];
            float  pbo = p_s[wid * 2 + 1][jj + 1];
            float2 ve = *(const float2*)&vv_s[jj][2 * lane];
            float2 vo = *(const float2*)&vv_s[jj + 1][2 * lane];
            axe = fmaf(pae, ve.x, axe);
            aye = fmaf(pae, ve.y, aye);
            axo = fmaf(pao, vo.x, axo);
            ayo = fmaf(pao, vo.y, ayo);
            bxe = fmaf(pbe, ve.x, bxe);
            bye = fmaf(pbe, ve.y, bye);
            bxo = fmaf(pbo, vo.x, bxo);
            byo = fmaf(pbo, vo.y, byo);
        }
    }

    // final cross-lane sums of la, lb (once per kernel)
    float lta = la, ltb = lb;
    #pragma unroll
    for (int off = 16; off; off >>= 1) {
        lta += __shfl_xor_sync(0xffffffffu, lta, off);
        ltb += __shfl_xor_sync(0xffffffffu, ltb, off);
    }

    float inva = 1.0f / lta;
    float invb = 1.0f / ltb;
    *(float2*)&out[(b * TT + ia) * DD + 2 * lane] =
        make_float2((axe + axo) * inva, (aye + ayo) * inva);
    *(float2*)&out[(b * TT + ib) * DD + 2 * lane] =
        make_float2((bxe + bxo) * invb, (bye + byo) * invb);
}

// ---------------------------------------------------------------------------
extern "C" void kernel_launch(void* const* d_in, const int* in_sizes, int n_in,
                              void* d_out, int out_size)
{
    const float* x  = (const float*)d_in[0];
    const float* Wq = (const float*)d_in[1];
    const float* bq = (const float*)d_in[2];
    const float* Wk = (const float*)d_in[3];
    const float* bk = (const float*)d_in[4];
    const float* Wv = (const float*)d_in[5];
    const float* bv = (const float*)d_in[6];
    const float* W1 = (const float*)d_in[7];
    const float* b1 = (const float*)d_in[8];
    const float* W2 = (const float*)d_in[9];
    // b2 (d_in[10]) is a constant shift on scores: cancels in softmax.

    (void)cudaFuncSetAttribute(attn_kernel,
                               cudaFuncAttributeMaxDynamicSharedMemorySize,
                               SMEM_BYTES);

    proj_kernel<<<BB * TT / 2, 64>>>(x, Wq, bq, Wk, bk, Wv, bv, W1, b1);
    attn_kernel<<<BB * TT / 4, 64, SMEM_BYTES>>>(W2, (float*)d_out);
}

// round 7
// speedup vs baseline: 2.0333x; 1.0748x over previous
#include <cuda_runtime.h>

#define TT 1024
#define EE 256
#define DD 64
#define BB 2
#define JCH 64        // keys per chunk
#define PROWS 16      // rows per proj block

// Scratch (device globals: no allocation allowed in kernel_launch)
__device__ float g_qpb[BB * TT * DD];   // qp + b1, row-major [row][d]
__device__ float g_kpT[BB * DD * TT];   // kp transposed   [b][d][t]
__device__ float g_v  [BB * TT * DD];   // v, row-major    [row][dv]
// split-K partials
__device__ float g_po[2][BB * TT * DD]; // unnormalized o
__device__ float g_pm[2][BB * TT];      // running max
__device__ float g_pl[2][BB * TT];      // denominator

__device__ __forceinline__ void cp16(float* dst, const float* src) {
    unsigned d = (unsigned)__cvta_generic_to_shared(dst);
    asm volatile("cp.async.cg.shared.global [%0], [%1], 16;" :: "r"(d), "l"(src));
}
__device__ __forceinline__ void cp_commit() { asm volatile("cp.async.commit_group;"); }
__device__ __forceinline__ void cp_wait_all() { asm volatile("cp.async.wait_group 0;"); }

// Warp-wide float max via integer redux.sync (f32 redux doesn't exist).
__device__ __forceinline__ float warp_max_f32(float x) {
    unsigned ix = __float_as_uint(x);
    ix = (ix & 0x80000000u) ? ~ix : (ix | 0x80000000u);
    unsigned r = __reduce_max_sync(0xffffffffu, ix);
    r = (r & 0x80000000u) ? (r & 0x7fffffffu) : ~r;
    return __uint_as_float(r);
}

// ---------------------------------------------------------------------------
// Kernel 1: fused projections. 16 rows/block x 128 blocks x 192 threads.
// Weight L2 traffic: 128 blocks x 192KB = 24MB (was ~196MB).
// Phase A thread = (which[3], d4[16], rg[4]): 4 rows x 4 cols.
// ---------------------------------------------------------------------------
__global__ __launch_bounds__(192) void proj_kernel(
    const float* __restrict__ x,
    const float* __restrict__ Wq, const float* __restrict__ bq,
    const float* __restrict__ Wk, const float* __restrict__ bk,
    const float* __restrict__ Wv, const float* __restrict__ bv,
    const float* __restrict__ W1, const float* __restrict__ b1)
{
    __shared__ float x_s[PROWS][EE];   // 16KB
    __shared__ float q_s[PROWS][DD];   // 4KB
    __shared__ float k_s[PROWS][DD];   // 4KB

    const int r0 = blockIdx.x * PROWS;
    const int t  = threadIdx.x;

    for (int idx = t; idx < PROWS * EE / 4; idx += 192)
        ((float4*)x_s)[idx] = ((const float4*)(x + r0 * EE))[idx];
    __syncthreads();

    // ---- Phase A: q,k,v ----
    {
        const int which = t >> 6;          // 0..2
        const int d4    = (t >> 2) & 15;   // 0..15
        const int rg    = t & 3;           // 0..3 -> rows rg*4..rg*4+3
        const float4* W4 = (const float4*)(which == 0 ? Wq : (which == 1 ? Wk : Wv));
        const float4* b4 = (const float4*)(which == 0 ? bq : (which == 1 ? bk : bv));

        float4 acc[4];
        #pragma unroll
        for (int r = 0; r < 4; r++) acc[r] = make_float4(0.f, 0.f, 0.f, 0.f);

        for (int e = 0; e < EE; e++) {
            float4 w = W4[e * 16 + d4];
            #pragma unroll
            for (int r = 0; r < 4; r++) {
                float xv = x_s[rg * 4 + r][e];
                acc[r].x = fmaf(xv, w.x, acc[r].x);
                acc[r].y = fmaf(xv, w.y, acc[r].y);
                acc[r].z = fmaf(xv, w.z, acc[r].z);
                acc[r].w = fmaf(xv, w.w, acc[r].w);
            }
        }
        float4 bias = b4[d4];
        #pragma unroll
        for (int r = 0; r < 4; r++) {
            int row = rg * 4 + r;
            float4 o;
            o.x = acc[r].x + bias.x;
            o.y = acc[r].y + bias.y;
            o.z = acc[r].z + bias.z;
            o.w = acc[r].w + bias.w;
            if (which == 2) {
                *(float4*)&g_v[(r0 + row) * DD + d4 * 4] = o;
            } else {
                o.x = fmaxf(o.x, 0.f);
                o.y = fmaxf(o.y, 0.f);
                o.z = fmaxf(o.z, 0.f);
                o.w = fmaxf(o.w, 0.f);
                if (which == 0) *(float4*)&q_s[row][d4 * 4] = o;
                else            *(float4*)&k_s[row][d4 * 4] = o;
            }
        }
    }
    __syncthreads();

    // ---- Phase B: qp (with b1) and kp ----
    if (t < 128) {
        const int sel = t >> 6;            // 0 = qp, 1 = kp
        const int d4  = (t >> 2) & 15;
        const int rg  = t & 3;

        float4 acc[4];
        #pragma unroll
        for (int r = 0; r < 4; r++) acc[r] = make_float4(0.f, 0.f, 0.f, 0.f);

        const float (*src)[DD] = (sel == 0) ? q_s : k_s;
        const float4* W14 = (const float4*)W1 + sel * 64 * 16;

        for (int dd = 0; dd < DD; dd++) {
            float4 w = W14[dd * 16 + d4];
            #pragma unroll
            for (int r = 0; r < 4; r++) {
                float qv = src[rg * 4 + r][dd];
                acc[r].x = fmaf(qv, w.x, acc[r].x);
                acc[r].y = fmaf(qv, w.y, acc[r].y);
                acc[r].z = fmaf(qv, w.z, acc[r].z);
                acc[r].w = fmaf(qv, w.w, acc[r].w);
            }
        }

        if (sel == 0) {
            float4 bias = ((const float4*)b1)[d4];
            #pragma unroll
            for (int r = 0; r < 4; r++) {
                float4 o;
                o.x = acc[r].x + bias.x;
                o.y = acc[r].y + bias.y;
                o.z = acc[r].z + bias.z;
                o.w = acc[r].w + bias.w;
                *(float4*)&g_qpb[(r0 + rg * 4 + r) * DD + d4 * 4] = o;
            }
        } else {
            const int b  = r0 >> 10;
            const int tb = (r0 & 1023) + rg * 4;     // 4 consecutive t-rows
            float4 c0 = make_float4(acc[0].x, acc[1].x, acc[2].x, acc[3].x);
            float4 c1 = make_float4(acc[0].y, acc[1].y, acc[2].y, acc[3].y);
            float4 c2 = make_float4(acc[0].z, acc[1].z, acc[2].z, acc[3].z);
            float4 c3 = make_float4(acc[0].w, acc[1].w, acc[2].w, acc[3].w);
            *(float4*)&g_kpT[(b * DD + d4 * 4 + 0) * TT + tb] = c0;
            *(float4*)&g_kpT[(b * DD + d4 * 4 + 1) * TT + tb] = c1;
            *(float4*)&g_kpT[(b * DD + d4 * 4 + 2) * TT + tb] = c2;
            *(float4*)&g_kpT[(b * DD + d4 * 4 + 3) * TT + tb] = c3;
        }
    }
}

// ---------------------------------------------------------------------------
// Kernel 2: split-K attention partials. 2 blocks per query-quad; block s
// handles chunks s, s+2, s+4, ... (stride-2 keeps cp.async double-buffering).
// 2 queries/warp, 2 warps/block. Writes unnormalized (o, m, l) partials.
// ---------------------------------------------------------------------------
#define SMEM_FLOATS (2 * DD * JCH + 2 * JCH * DD + 4 * JCH + 4 * DD + DD + 4)
#define SMEM_BYTES  (SMEM_FLOATS * 4)

__global__ __launch_bounds__(64, 3) void attn_kernel(
    const float* __restrict__ W2)
{
    extern __shared__ __align__(16) float smem[];
    float (*kp_s)[DD][JCH] = (float (*)[DD][JCH])smem;                  // [2][d][j]
    float (*v_s)[JCH][DD]  = (float (*)[JCH][DD])(smem + 2 * DD * JCH); // [2][j][dv]
    float (*p_s)[JCH]      = (float (*)[JCH])(smem + 4 * DD * JCH);     // [4][j]
    float (*q_s)[DD]       = (float (*)[DD])(smem + 4 * DD * JCH + 4 * JCH); // [4][d]
    float *w2_s            = smem + 4 * DD * JCH + 4 * JCH + 4 * DD;

    const int bid  = (int)blockIdx.x;
    const int quad = ((int)gridDim.x / 2 - 1) - (bid >> 1);   // heavy-first
    const int s    = bid & 1;                                  // split id
    const int b    = quad >> 8;
    const int i0   = (quad & 255) * 4;
    const int t    = threadIdx.x;
    const int wid  = t >> 5;
    const int lane = t & 31;
    const int ia   = i0 + wid * 2;
    const int ib   = ia + 1;

    if (t < DD) w2_s[t] = W2[t];
    ((float4*)q_s)[t] = ((const float4*)(g_qpb + (b * TT + i0) * DD))[t];

    const float* kpT_b = g_kpT + b * DD * TT;
    const float* v_b   = g_v   + b * TT * DD;

    const int nch = i0 / JCH + 1;            // block-uniform

    // prefetch first chunk of this split (if any)
    if (s < nch) {
        const int j0 = s * JCH;
        #pragma unroll
        for (int u = 0; u < 16; u++) {
            int idx = t + u * 64;
            int d = idx >> 4, cc = idx & 15;
            cp16(&kp_s[0][d][cc * 4], kpT_b + d * TT + j0 + cc * 4);
            cp16(&v_s[0][0][0] + idx * 4, v_b + j0 * DD + idx * 4);
        }
    }
    cp_commit();

    const float NEG_INF = __int_as_float(0xff800000);
    float ma = NEG_INF, la = 0.f, mb = NEG_INF, lb = 0.f;
    float axe = 0.f, aye = 0.f, axo = 0.f, ayo = 0.f;
    float bxe = 0.f, bye = 0.f, bxo = 0.f, byo = 0.f;

    const float4* qa4 = (const float4*)q_s[wid * 2];
    const float4* qb4 = (const float4*)q_s[wid * 2 + 1];
    const float4* w24 = (const float4*)w2_s;

    for (int c = s; c < nch; c += 2) {
        cp_wait_all();
        __syncthreads();

        if (c + 2 < nch) {                    // prefetch c+2 into other buffer
            const int j0n = (c + 2) * JCH;
            const int buf = ((c >> 1) + 1) & 1;
            #pragma unroll
            for (int u = 0; u < 16; u++) {
                int idx = t + u * 64;
                int d = idx >> 4, cc = idx & 15;
                cp16(&kp_s[buf][d][cc * 4], kpT_b + d * TT + j0n + cc * 4);
                cp16(&v_s[buf][0][0] + idx * 4, v_b + j0n * DD + idx * 4);
            }
            cp_commit();
        }

        const int j0 = c * JCH;
        const int cb2 = (c >> 1) & 1;
        const float (*kp)[JCH] = kp_s[cb2];
        const float (*vv_s)[DD] = v_s[cb2];

        // ---- scores for keys j0+2*lane(+1), queries ia & ib ----
        float a0 = 0.f, a1 = 0.f, a2 = 0.f, a3 = 0.f;
        float b0 = 0.f, b1 = 0.f, b2 = 0.f, b3 = 0.f;
        #pragma unroll
        for (int d4 = 0; d4 < 16; d4++) {
            float4 w4 = w24[d4];
            float4 qa = qa4[d4];
            float4 qb = qb4[d4];
            float2 k0 = *(const float2*)&kp[4 * d4 + 0][2 * lane];
            float2 k1 = *(const float2*)&kp[4 * d4 + 1][2 * lane];
            float2 k2 = *(const float2*)&kp[4 * d4 + 2][2 * lane];
            float2 k3 = *(const float2*)&kp[4 * d4 + 3][2 * lane];
            a0 = fmaf(fmaxf(qa.x + k0.x, 0.f), w4.x, a0);
            a1 = fmaf(fmaxf(qa.x + k0.y, 0.f), w4.x, a1);
            a2 = fmaf(fmaxf(qa.y + k1.x, 0.f), w4.y, a2);
            a3 = fmaf(fmaxf(qa.y + k1.y, 0.f), w4.y, a3);
            a0 = fmaf(fmaxf(qa.z + k2.x, 0.f), w4.z, a0);
            a1 = fmaf(fmaxf(qa.z + k2.y, 0.f), w4.z, a1);
            a2 = fmaf(fmaxf(qa.w + k3.x, 0.f), w4.w, a2);
            a3 = fmaf(fmaxf(qa.w + k3.y, 0.f), w4.w, a3);
            b0 = fmaf(fmaxf(qb.x + k0.x, 0.f), w4.x, b0);
            b1 = fmaf(fmaxf(qb.x + k0.y, 0.f), w4.x, b1);
            b2 = fmaf(fmaxf(qb.y + k1.x, 0.f), w4.y, b2);
            b3 = fmaf(fmaxf(qb.y + k1.y, 0.f), w4.y, b3);
            b0 = fmaf(fmaxf(qb.z + k2.x, 0.f), w4.z, b0);
            b1 = fmaf(fmaxf(qb.z + k2.y, 0.f), w4.z, b1);
            b2 = fmaf(fmaxf(qb.w + k3.x, 0.f), w4.w, b2);
            b3 = fmaf(fmaxf(qb.w + k3.y, 0.f), w4.w, b3);
        }
        const int j = j0 + 2 * lane;
        float s0a = (j     <= ia) ? (a0 + a2) : NEG_INF;
        float s1a = (j + 1 <= ia) ? (a1 + a3) : NEG_INF;
        float s0b = (j     <= ib) ? (b0 + b2) : NEG_INF;
        float s1b = (j + 1 <= ib) ? (b1 + b3) : NEG_INF;

        // ---- online softmax (lane-local sums, one redux max per query) ----
        float nma  = fmaxf(ma, warp_max_f32(fmaxf(s0a, s1a)));
        float nmb  = fmaxf(mb, warp_max_f32(fmaxf(s0b, s1b)));
        float ca   = __expf(ma - nma);
        float cb   = __expf(mb - nmb);
        float p0a  = __expf(s0a - nma), p1a = __expf(s1a - nma);
        float p0b  = __expf(s0b - nmb), p1b = __expf(s1b - nmb);
        la = fmaf(la, ca, p0a + p1a);
        lb = fmaf(lb, cb, p0b + p1b);
        axe *= ca; aye *= ca; axo *= ca; ayo *= ca;
        bxe *= cb; bye *= cb; bxo *= cb; byo *= cb;
        ma = nma; mb = nmb;

        *(float2*)&p_s[wid * 2    ][2 * lane] = make_float2(p0a, p1a);
        *(float2*)&p_s[wid * 2 + 1][2 * lane] = make_float2(p0b, p1b);
        __syncwarp();

        // ---- PV: each v LDS.64 feeds both queries ----
        #pragma unroll
        for (int jj = 0; jj < JCH; jj += 2) {
            float  pae = p_s[wid * 2][jj];
            float  pao = p_s[wid * 2][jj + 1];
            float  pbe = p_s[wid * 2 + 1][jj];
            float  pbo = p_s[wid * 2 + 1][jj + 1];
            float2 ve = *(const float2*)&vv_s[jj][2 * lane];
            float2 vo = *(const float2*)&vv_s[jj + 1][2 * lane];
            axe = fmaf(pae, ve.x, axe);
            aye = fmaf(pae, ve.y, aye);
            axo = fmaf(pao, vo.x, axo);
            ayo = fmaf(pao, vo.y, ayo);
            bxe = fmaf(pbe, ve.x, bxe);
            bye = fmaf(pbe, ve.y, bye);
            bxo = fmaf(pbo, vo.x, bxo);
            byo = fmaf(pbo, vo.y, byo);
        }
    }

    // cross-lane denominator sums
    float lta = la, ltb = lb;
    #pragma unroll
    for (int off = 16; off; off >>= 1) {
        lta += __shfl_xor_sync(0xffffffffu, lta, off);
        ltb += __shfl_xor_sync(0xffffffffu, ltb, off);
    }

    // write partials (unnormalized)
    *(float2*)&g_po[s][(b * TT + ia) * DD + 2 * lane] = make_float2(axe + axo, aye + ayo);
    *(float2*)&g_po[s][(b * TT + ib) * DD + 2 * lane] = make_float2(bxe + bxo, bye + byo);
    if (lane == 0) {
        g_pm[s][b * TT + ia] = ma;  g_pl[s][b * TT + ia] = lta;
        g_pm[s][b * TT + ib] = mb;  g_pl[s][b * TT + ib] = ltb;
    }
}

// ---------------------------------------------------------------------------
// Kernel 3: combine the two split-K partials. 4 rows/block x 512 blocks.
// ---------------------------------------------------------------------------
__global__ __launch_bounds__(128) void combine_kernel(float* __restrict__ out)
{
    const int row  = blockIdx.x * 4 + (threadIdx.x >> 5);
    const int lane = threadIdx.x & 31;

    float m0 = g_pm[0][row], l0 = g_pl[0][row];
    float m1 = g_pm[1][row], l1 = g_pl[1][row];
    float M  = fmaxf(m0, m1);
    float c0 = __expf(m0 - M);
    float c1 = __expf(m1 - M);          // m1=-inf (empty split) -> c1=0
    float inv = 1.0f / fmaf(l0, c0, l1 * c1);

    float2 o0 = *(const float2*)&g_po[0][row * DD + 2 * lane];
    float2 o1 = *(const float2*)&g_po[1][row * DD + 2 * lane];
    *(float2*)&out[row * DD + 2 * lane] =
        make_float2(fmaf(o0.x, c0, o1.x * c1) * inv,
                    fmaf(o0.y, c0, o1.y * c1) * inv);
}

// ---------------------------------------------------------------------------
extern "C" void kernel_launch(void* const* d_in, const int* in_sizes, int n_in,
                              void* d_out, int out_size)
{
    const float* x  = (const float*)d_in[0];
    const float* Wq = (const float*)d_in[1];
    const float* bq = (const float*)d_in[2];
    const float* Wk = (const float*)d_in[3];
    const float* bk = (const float*)d_in[4];
    const float* Wv = (const float*)d_in[5];
    const float* bv = (const float*)d_in[6];
    const float* W1 = (const float*)d_in[7];
    const float* b1 = (const float*)d_in[8];
    const float* W2 = (const float*)d_in[9];
    // b2 (d_in[10]) is a constant shift on scores: cancels in softmax.

    (void)cudaFuncSetAttribute(attn_kernel,
                               cudaFuncAttributeMaxDynamicSharedMemorySize,
                               SMEM_BYTES);

    proj_kernel<<<BB * TT / PROWS, 192>>>(x, Wq, bq, Wk, bk, Wv, bv, W1, b1);
    attn_kernel<<<BB * TT / 4 * 2, 64, SMEM_BYTES>>>(W2);
    combine_kernel<<<BB * TT / 4, 128>>>((float*)d_out);
}